// round 1
// baseline (speedup 1.0000x reference)
#include <cuda_runtime.h>
#include <cstdint>
#include <cmath>

// Problem constants
#define T_TOK 1024
#define HDIM  2048
#define NEXP  64
#define IDIM  1024
#define SIDIM 4096
#define KSEL  8
#define NROWS (T_TOK * KSEL)   // 8192 routed (token, expert) rows

// ---------------------------------------------------------------------------
// Device-global scratch (allocation-free contract: __device__ arrays only)
// ---------------------------------------------------------------------------
__device__ float g_gu[(long)NROWS * 2 * IDIM];    // MoE gate_up output  [8192, 2048]
__device__ float g_h[(long)NROWS * IDIM];         // MoE silu*mul        [8192, 1024]
__device__ float g_down[(long)NROWS * HDIM];      // MoE down output     [8192, 2048]
__device__ float g_gu_s[(long)T_TOK * 2 * SIDIM]; // shared gate_up      [1024, 8192]
__device__ float g_h_s[(long)T_TOK * SIDIM];      // shared act          [1024, 4096]
__device__ float g_sh_out[(long)T_TOK * HDIM];    // shared MLP out      [1024, 2048]

__device__ int   g_counts[NEXP];
__device__ int   g_offsets[NEXP];
__device__ int   g_fill[NEXP];
__device__ int   g_rowmap[NROWS];      // packed row -> token id
__device__ int   g_row_of_tk[NROWS];   // (t,k) -> packed row
__device__ int   g_top_e[NROWS];
__device__ float g_top_w[NROWS];

// ---------------------------------------------------------------------------
// Small helpers (cp.async, tf32 cvt, mma)
// ---------------------------------------------------------------------------
__device__ __forceinline__ void cp_async16(void* smem, const void* gmem, int src_bytes) {
    uint32_t s = (uint32_t)__cvta_generic_to_shared(smem);
    asm volatile("cp.async.cg.shared.global [%0], [%1], 16, %2;\n"
                 :: "r"(s), "l"(gmem), "r"(src_bytes));
}
__device__ __forceinline__ void cp_commit() { asm volatile("cp.async.commit_group;\n"); }
__device__ __forceinline__ void cp_wait0()  { asm volatile("cp.async.wait_group 0;\n"); }

__device__ __forceinline__ uint32_t f2tf(float f) {
    uint32_t r;
    asm("cvt.rna.tf32.f32 %0, %1;" : "=r"(r) : "f"(f));
    return r;
}

__device__ __forceinline__ void mma_tf32(float c[4],
                                         uint32_t a0, uint32_t a1, uint32_t a2, uint32_t a3,
                                         uint32_t b0, uint32_t b1) {
    asm volatile(
        "mma.sync.aligned.m16n8k8.row.col.f32.tf32.tf32.f32 "
        "{%0,%1,%2,%3},{%4,%5,%6,%7},{%8,%9},{%0,%1,%2,%3};\n"
        : "+f"(c[0]), "+f"(c[1]), "+f"(c[2]), "+f"(c[3])
        : "r"(a0), "r"(a1), "r"(a2), "r"(a3), "r"(b0), "r"(b1));
}

// ---------------------------------------------------------------------------
// 1) init / router / scan / assign
// ---------------------------------------------------------------------------
__global__ void init_k() {
    int i = threadIdx.x;
    if (i < NEXP) g_counts[i] = 0;
}

__global__ void router_k(const float* __restrict__ x, const float* __restrict__ wg) {
    int t = blockIdx.x;
    __shared__ float xs[HDIM];
    __shared__ float sc[NEXP];
    for (int d = threadIdx.x; d < HDIM; d += blockDim.x) xs[d] = x[(long)t * HDIM + d];
    __syncthreads();

    int w = threadIdx.x >> 5, lane = threadIdx.x & 31;
    for (int e = w * 8; e < w * 8 + 8; e++) {
        const float* wr = wg + (long)e * HDIM;
        float s = 0.f;
        for (int d = lane; d < HDIM; d += 32) s += xs[d] * wr[d];
        #pragma unroll
        for (int o = 16; o; o >>= 1) s += __shfl_xor_sync(0xffffffffu, s, o);
        if (lane == 0) sc[e] = 1.f / (1.f + expf(-s));
    }
    __syncthreads();

    if (threadIdx.x == 0) {
        for (int k = 0; k < KSEL; k++) {
            int best = 0; float bv = sc[0];
            for (int e = 1; e < NEXP; e++) {
                if (sc[e] > bv) { bv = sc[e]; best = e; }   // strict > : first index wins ties
            }
            g_top_e[t * KSEL + k] = best;
            g_top_w[t * KSEL + k] = bv;
            atomicAdd(&g_counts[best], 1);
            sc[best] = -1.f;
        }
    }
}

__global__ void scan_k() {
    if (threadIdx.x == 0) {
        int acc = 0;
        for (int e = 0; e < NEXP; e++) {
            g_offsets[e] = acc;
            g_fill[e] = acc;
            acc += g_counts[e];
        }
    }
}

__global__ void assign_k() {
    int idx = blockIdx.x * blockDim.x + threadIdx.x;
    if (idx >= NROWS) return;
    int e = g_top_e[idx];
    int r = atomicAdd(&g_fill[e], 1);
    g_rowmap[r] = idx >> 3;       // token
    g_row_of_tk[idx] = r;
}

// ---------------------------------------------------------------------------
// 2) TF32 tensor-core GEMM:  C[m,n] = sum_k A[m,k] * B[n,k]
//    BM=128, BN=64, BK=16, 256 threads (8 warps, 4x2 warp grid, 32x32/warp)
//    cp.async double-buffered; SMEM stride 20 floats (conflict-free & 16B-aligned)
// ---------------------------------------------------------------------------
template <bool GATHER, bool EXPERT>
__global__ void __launch_bounds__(256)
gemm_k(const float* __restrict__ A, const float* __restrict__ Bb, float* __restrict__ C,
       int N, int Kd, long strideBe, int Mdense)
{
    int e = EXPERT ? blockIdx.z : 0;
    int M, off;
    if (EXPERT) { M = g_counts[e]; off = g_offsets[e]; }
    else        { M = Mdense;      off = 0; }

    int m0 = blockIdx.y * 128;
    if (m0 >= M) return;
    int n0 = blockIdx.x * 64;
    const float* B = Bb + (long)e * strideBe;

    __shared__ float As[2][128 * 20];
    __shared__ float Bs[2][64 * 20];
    __shared__ int   arows[128];

    int tid = threadIdx.x;
    if (tid < 128) {
        int gr = m0 + tid;
        int ar = -1;
        if (gr < M) ar = GATHER ? g_rowmap[off + gr] : (off + gr);
        arows[tid] = ar;
    }
    __syncthreads();

    // load slots
    int a_r0 = tid >> 2;             // rows 0..63
    int a_r1 = (tid >> 2) + 64;      // rows 64..127
    int a_c  = tid & 3;              // float4 column within 16-wide row
    int b_r  = tid >> 2;             // 0..63
    int b_c  = tid & 3;

    auto load_tile = [&](int kt, int buf) {
        int k0 = kt * 16;
        {
            int ar = arows[a_r0];
            cp_async16(&As[buf][a_r0 * 20 + a_c * 4],
                       ar >= 0 ? (A + (long)ar * Kd + k0 + a_c * 4) : A,
                       ar >= 0 ? 16 : 0);
            int ar1 = arows[a_r1];
            cp_async16(&As[buf][a_r1 * 20 + a_c * 4],
                       ar1 >= 0 ? (A + (long)ar1 * Kd + k0 + a_c * 4) : A,
                       ar1 >= 0 ? 16 : 0);
        }
        {
            int bn = n0 + b_r;
            cp_async16(&Bs[buf][b_r * 20 + b_c * 4],
                       B + (long)bn * Kd + k0 + b_c * 4, 16);
        }
        cp_commit();
    };

    int warp = tid >> 5, lane = tid & 31;
    int wm = warp & 3;      // 4 warps along M, 32 rows each
    int wn = warp >> 2;     // 2 warps along N, 32 cols each
    int g  = lane >> 2, tg = lane & 3;

    float acc[2][4][4];
    #pragma unroll
    for (int i = 0; i < 2; i++)
        #pragma unroll
        for (int j = 0; j < 4; j++)
            #pragma unroll
            for (int q = 0; q < 4; q++) acc[i][j][q] = 0.f;

    int ktiles = Kd >> 4;
    load_tile(0, 0);
    cp_wait0();
    __syncthreads();

    for (int kt = 0; kt < ktiles; kt++) {
        int buf = kt & 1;
        if (kt + 1 < ktiles) load_tile(kt + 1, buf ^ 1);

        #pragma unroll
        for (int kk = 0; kk < 16; kk += 8) {
            uint32_t afr[2][4];
            #pragma unroll
            for (int mi = 0; mi < 2; mi++) {
                int rb = wm * 32 + mi * 16;
                const float* as = &As[buf][0];
                afr[mi][0] = f2tf(as[(rb + g    ) * 20 + kk + tg    ]);
                afr[mi][1] = f2tf(as[(rb + g + 8) * 20 + kk + tg    ]);
                afr[mi][2] = f2tf(as[(rb + g    ) * 20 + kk + tg + 4]);
                afr[mi][3] = f2tf(as[(rb + g + 8) * 20 + kk + tg + 4]);
            }
            #pragma unroll
            for (int ni = 0; ni < 4; ni++) {
                int nb = wn * 32 + ni * 8;
                uint32_t b0 = f2tf(Bs[buf][(nb + g) * 20 + kk + tg    ]);
                uint32_t b1 = f2tf(Bs[buf][(nb + g) * 20 + kk + tg + 4]);
                #pragma unroll
                for (int mi = 0; mi < 2; mi++)
                    mma_tf32(acc[mi][ni], afr[mi][0], afr[mi][1], afr[mi][2], afr[mi][3], b0, b1);
            }
        }
        cp_wait0();
        __syncthreads();
    }

    // epilogue
    #pragma unroll
    for (int mi = 0; mi < 2; mi++) {
        int r0 = m0 + wm * 32 + mi * 16 + g;
        #pragma unroll
        for (int ni = 0; ni < 4; ni++) {
            int col = n0 + wn * 32 + ni * 8 + tg * 2;
            if (r0 < M) {
                C[(long)(off + r0) * N + col    ] = acc[mi][ni][0];
                C[(long)(off + r0) * N + col + 1] = acc[mi][ni][1];
            }
            if (r0 + 8 < M) {
                C[(long)(off + r0 + 8) * N + col    ] = acc[mi][ni][2];
                C[(long)(off + r0 + 8) * N + col + 1] = acc[mi][ni][3];
            }
        }
    }
}

// ---------------------------------------------------------------------------
// 3) activations + combine
// ---------------------------------------------------------------------------
__global__ void moe_act_k() {
    long idx = (long)blockIdx.x * 256 + threadIdx.x;
    if (idx >= (long)NROWS * IDIM) return;
    long r = idx >> 10;             // IDIM = 1024
    int  i = (int)(idx & 1023);
    float gv = g_gu[r * 2048 + i];
    float uv = g_gu[r * 2048 + 1024 + i];
    g_h[idx] = gv * uv / (1.f + expf(-gv));
}

__global__ void shared_act_k() {
    long idx = (long)blockIdx.x * 256 + threadIdx.x;
    if (idx >= (long)T_TOK * SIDIM) return;
    long r = idx >> 12;             // SIDIM = 4096
    int  i = (int)(idx & 4095);
    float gv = g_gu_s[r * 8192 + i];
    float uv = g_gu_s[r * 8192 + 4096 + i];
    g_h_s[idx] = gv * uv / (1.f + expf(-gv));
}

__global__ void combine_k(float* __restrict__ out) {
    int t = blockIdx.x;
    __shared__ int   rws[KSEL];
    __shared__ float ws[KSEL];
    if (threadIdx.x < KSEL) {
        rws[threadIdx.x] = g_row_of_tk[t * KSEL + threadIdx.x];
        ws[threadIdx.x]  = g_top_w[t * KSEL + threadIdx.x];
    }
    __syncthreads();
    for (int d = threadIdx.x; d < HDIM; d += blockDim.x) {
        float a = g_sh_out[(long)t * HDIM + d];
        float m = 0.f;
        #pragma unroll
        for (int k = 0; k < KSEL; k++)
            m += ws[k] * g_down[(long)rws[k] * HDIM + d];
        out[(long)t * HDIM + d] = (a + 8.f * m) * (1.f / 9.f);
    }
}

// ---------------------------------------------------------------------------
// kernel_launch — graph-capturable, allocation-free
// ---------------------------------------------------------------------------
extern "C" void kernel_launch(void* const* d_in, const int* in_sizes, int n_in,
                              void* d_out, int out_size)
{
    const float* x      = (const float*)d_in[0];
    const float* w_gate = (const float*)d_in[1];
    const float* w13    = (const float*)d_in[2];
    const float* w2     = (const float*)d_in[3];
    const float* wsg    = (const float*)d_in[4];
    const float* wsd    = (const float*)d_in[5];
    float* out = (float*)d_out;

    // scratch pointers (symbol lookup is not an allocation; host code runs only at capture)
    float *p_gu, *p_h, *p_down, *p_gu_s, *p_h_s, *p_sh_out;
    cudaGetSymbolAddress((void**)&p_gu,     g_gu);
    cudaGetSymbolAddress((void**)&p_h,      g_h);
    cudaGetSymbolAddress((void**)&p_down,   g_down);
    cudaGetSymbolAddress((void**)&p_gu_s,   g_gu_s);
    cudaGetSymbolAddress((void**)&p_h_s,    g_h_s);
    cudaGetSymbolAddress((void**)&p_sh_out, g_sh_out);

    // routing
    init_k<<<1, 64>>>();
    router_k<<<T_TOK, 256>>>(x, w_gate);
    scan_k<<<1, 32>>>();
    assign_k<<<NROWS / 256, 256>>>();

    // MoE gate_up: [8192, 2048] = gather(x) @ w13[e]^T   (K = 2048)
    gemm_k<true, true><<<dim3(2 * IDIM / 64, 8, NEXP), 256>>>(
        x, w13, p_gu, 2 * IDIM, HDIM, (long)2 * IDIM * HDIM, 0);

    moe_act_k<<<(NROWS * IDIM) / 256, 256>>>();

    // MoE down: [8192, 2048] = h @ w2[e]^T               (K = 1024)
    gemm_k<false, true><<<dim3(HDIM / 64, 8, NEXP), 256>>>(
        p_h, w2, p_down, HDIM, IDIM, (long)HDIM * IDIM, 0);

    // Shared gate_up: [1024, 8192] = x @ wsg^T           (K = 2048)
    gemm_k<false, false><<<dim3(2 * SIDIM / 64, T_TOK / 128, 1), 256>>>(
        x, wsg, p_gu_s, 2 * SIDIM, HDIM, 0, T_TOK);

    shared_act_k<<<(T_TOK * SIDIM) / 256, 256>>>();

    // Shared down: [1024, 2048] = h_s @ wsd^T            (K = 4096)
    gemm_k<false, false><<<dim3(HDIM / 64, T_TOK / 128, 1), 256>>>(
        p_h_s, wsd, p_sh_out, HDIM, SIDIM, 0, T_TOK);

    // Combine: (shared + K * sum_k w_k * down_row_k) / (K+1)
    combine_k<<<T_TOK, 256>>>(out);
}